// round 11
// baseline (speedup 1.0000x reference)
#include <cuda_runtime.h>
#include <math.h>
#include <stdint.h>

#define BSZ    2
#define SEQ    2048
#define DMODEL 2048
#define NHEADS 16
#define HDIM   128
#define BH     (BSZ*NHEADS)
#define MROWS  (BSZ*SEQ)

// ---- scratch ----
__device__ float g_q[BH*SEQ*HDIM];
__device__ float g_k[BH*SEQ*HDIM];
__device__ float g_v[BH*SEQ*HDIM];
__device__ float g_attn[MROWS*DMODEL];
__device__ float g_ht[MROWS*DMODEL];        // tf32-rounded hidden
__device__ float g_wq[DMODEL*DMODEL];       // tf32-rounded weights
__device__ float g_wk[DMODEL*DMODEL];
__device__ float g_wv[DMODEL*DMODEL];
__device__ float g_wo[DMODEL*DMODEL];
__device__ float g_cos[SEQ*64];
__device__ float g_sin[SEQ*64];

__device__ __forceinline__ float to_tf32(float x) {
    float y;
    asm("cvt.rna.tf32.f32 %0, %1;" : "=f"(y) : "f"(x));
    return y;
}
__device__ __forceinline__ void mma_tf32(float* c, const uint32_t* a, const uint32_t* b) {
    asm volatile(
        "mma.sync.aligned.m16n8k8.row.col.f32.tf32.tf32.f32 "
        "{%0,%1,%2,%3}, {%4,%5,%6,%7}, {%8,%9}, {%0,%1,%2,%3};"
        : "+f"(c[0]), "+f"(c[1]), "+f"(c[2]), "+f"(c[3])
        : "r"(a[0]), "r"(a[1]), "r"(a[2]), "r"(a[3]), "r"(b[0]), "r"(b[1]));
}
__device__ __forceinline__ float4 tf32x4(float4 v) {
    v.x = to_tf32(v.x); v.y = to_tf32(v.y); v.z = to_tf32(v.z); v.w = to_tf32(v.w);
    return v;
}
__device__ __forceinline__ uint32_t smem_u32(const void* p) {
    uint32_t a;
    asm("{ .reg .u64 t; cvta.to.shared.u64 t, %1; cvt.u32.u64 %0, t; }" : "=r"(a) : "l"(p));
    return a;
}
__device__ __forceinline__ void cp16(uint32_t dst, const void* src) {
    asm volatile("cp.async.cg.shared.global [%0], [%1], 16;" :: "r"(dst), "l"(src));
}
__device__ __forceinline__ void cp_commit() {
    asm volatile("cp.async.commit_group;" ::: "memory");
}
__device__ __forceinline__ void cp_wait2() {
    asm volatile("cp.async.wait_group 2;" ::: "memory");
}

// =================== tf32 pre-round ===================
__global__ void cvt_tf32_kernel(const float4* __restrict__ src, float4* __restrict__ dst, int n4) {
    int i = blockIdx.x * blockDim.x + threadIdx.x;
    if (i < n4) dst[i] = tf32x4(src[i]);
}

// =================== RoPE ===================
__global__ void rope_cache_kernel() {
    int idx = blockIdx.x * blockDim.x + threadIdx.x;
    if (idx >= SEQ * 64) return;
    int pos = idx >> 6, j = idx & 63;
    double e    = (double)(2 * j) / 128.0;
    double invf = pow(10000.0, -e);
    double ang  = (double)pos * invf;
    g_cos[idx] = (float)cos(ang);
    g_sin[idx] = (float)sin(ang);
}
__global__ void rope_apply_kernel() {
    int idx = blockIdx.x * blockDim.x + threadIdx.x;
    if (idx >= BH * SEQ * 64) return;
    int j = idx & 63, row = idx >> 6, s = row & (SEQ - 1);
    float c = g_cos[s * 64 + j], sn = g_sin[s * 64 + j];
    float* qp = g_q + (size_t)row * HDIM;
    float* kp = g_k + (size_t)row * HDIM;
    float q1 = qp[j], q2 = qp[j + 64];
    qp[j]      = to_tf32(q1 * c - q2 * sn);
    qp[j + 64] = to_tf32(q2 * c + q1 * sn);
    float k1 = kp[j], k2 = kp[j + 64];
    kp[j]      = to_tf32(k1 * c - k2 * sn);
    kp[j + 64] = to_tf32(k2 * c + k1 * sn);
}

// =================== TF32 GEMM: e-plane frags + cp.async 4-stage ring ===================
// All operands pre-rounded to tf32. C[m,n] = sum_k A[m,k]*B[n,k].
// 128x128 CTA tile, K stage 16, 8 warps (2m x 4n), warp tile 64x32.
#define GEMM_K  DMODEL
#define KSTAGES (GEMM_K / 16)    // 128
#define AE 36
#define AT 144
#define BE 40
#define BT 80
#define A_STAGE (16*AT)          // 2304 words
#define B_STAGE (32*BT)          // 2560 words
#define NSTG 4
#define STAGE_WORDS (A_STAGE + B_STAGE)            // 4864
#define STAGE_BYTES (STAGE_WORDS * 4)              // 19456
#define GEMM_SMEM_BYTES (NSTG * STAGE_BYTES)       // 77824

__global__ __launch_bounds__(256, 2)
void tf32_gemm(const float* __restrict__ A,
               const float* __restrict__ B0, const float* __restrict__ B1,
               const float* __restrict__ B2,
               float* __restrict__ C0, float* __restrict__ C1, float* __restrict__ C2,
               int mode)
{
    extern __shared__ float smem[];

    const int z = blockIdx.z;
    const float* B = (z == 0) ? B0 : (z == 1) ? B1 : B2;
    float* C       = (z == 0) ? C0 : (z == 1) ? C1 : C2;

    const int tid  = threadIdx.x;
    const int wid  = tid >> 5;
    const int lane = tid & 31;
    const int bm = blockIdx.y * 128;
    const int bn = blockIdx.x * 128;
    const int wm = wid >> 2;
    const int wn = wid & 3;
    const uint32_t smb = smem_u32(smem);

    // fill mapping: 2 x 16B chunks per operand per thread per stage
    uint32_t aS[2], bS[2];
    const char* aG[2];
    const char* bG[2];
#pragma unroll
    for (int i = 0; i < 2; i++) {
        int f = i * 256 + tid;
        int row = f >> 2, c4 = f & 3;
        int kb = c4 >> 1, kh = c4 & 1;
        int g = row & 7, hi = (row >> 3) & 1;
        int mt = row >> 4, nt = row >> 3;
        aS[i] = smb + (uint32_t)(((mt * 2 + kb) * AT + (hi + 2 * kh) * AE + g * 4) * 4);
        bS[i] = smb + (uint32_t)((A_STAGE + (nt * 2 + kb) * BT + kh * BE + g * 4) * 4);
        aG[i] = (const char*)(A + (size_t)(bm + row) * GEMM_K + c4 * 4);
        bG[i] = (const char*)(B + (size_t)(bn + row) * GEMM_K + c4 * 4);
    }

#define FILL(ks_) do {                                               \
        uint32_t off_ = (uint32_t)(((ks_) & (NSTG - 1)) * STAGE_BYTES); \
        size_t go_ = (size_t)(ks_) * 64;                             \
        _Pragma("unroll")                                            \
        for (int i_ = 0; i_ < 2; i_++) {                             \
            cp16(aS[i_] + off_, aG[i_] + go_);                       \
            cp16(bS[i_] + off_, bG[i_] + go_);                       \
        }                                                            \
    } while (0)

    FILL(0); cp_commit();
    FILL(1); cp_commit();
    FILL(2); cp_commit();

    float acc[4][4][4];
#pragma unroll
    for (int mt = 0; mt < 4; mt++)
#pragma unroll
        for (int nt = 0; nt < 4; nt++)
#pragma unroll
            for (int e = 0; e < 4; e++) acc[mt][nt][e] = 0.f;

    const int aT0 = (wm * 4) * 2 * AT;
    const int bT0 = (wn * 4) * 2 * BT;

#pragma unroll 1
    for (int ks = 0; ks < KSTAGES; ks++) {
        cp_wait2();
        __syncthreads();
        if (ks + 3 < KSTAGES) FILL(ks + 3);
        cp_commit();

        const float* As_ = smem + (ks & (NSTG - 1)) * STAGE_WORDS;
        const float* Bs_ = As_ + A_STAGE;
#pragma unroll
        for (int kb = 0; kb < 2; kb++) {
            uint32_t a[4][4], b[4][2];
#pragma unroll
            for (int mt = 0; mt < 4; mt++)
#pragma unroll
                for (int e = 0; e < 4; e++)
                    a[mt][e] = __float_as_uint(As_[aT0 + (mt * 2 + kb) * AT + e * AE + lane]);
#pragma unroll
            for (int nt = 0; nt < 4; nt++)
#pragma unroll
                for (int e = 0; e < 2; e++)
                    b[nt][e] = __float_as_uint(Bs_[bT0 + (nt * 2 + kb) * BT + e * BE + lane]);
#pragma unroll
            for (int mt = 0; mt < 4; mt++)
#pragma unroll
                for (int nt = 0; nt < 4; nt++)
                    mma_tf32(acc[mt][nt], a[mt], b[nt]);
        }
    }
#undef FILL

    // epilogue (mode 1: round to tf32 — V consumed directly, Q/K re-rounded by RoPE)
    const int g = lane >> 2, tig = lane & 3;
#pragma unroll
    for (int mt = 0; mt < 4; mt++) {
#pragma unroll
        for (int nt = 0; nt < 4; nt++) {
            int row = bm + wm * 64 + mt * 16 + g;
            int col = bn + wn * 32 + nt * 8 + tig * 2;
            float* c0;
            size_t rstride;
            float e0 = acc[mt][nt][0], e1 = acc[mt][nt][1];
            float e2 = acc[mt][nt][2], e3 = acc[mt][nt][3];
            if (mode == 0) {
                c0 = C + (size_t)row * DMODEL + col;
                rstride = DMODEL;
            } else {
                int b = row >> 11, s = row & (SEQ - 1);
                int h = col >> 7, hd = col & 127;
                c0 = C + (((size_t)(b * NHEADS + h)) * SEQ + s) * HDIM + hd;
                rstride = HDIM;
                e0 = to_tf32(e0); e1 = to_tf32(e1);
                e2 = to_tf32(e2); e3 = to_tf32(e3);
            }
            *(float2*)c0 = make_float2(e0, e1);
            *(float2*)(c0 + 8 * rstride) = make_float2(e2, e3);
        }
    }
}

// =================== Flash attention (register-resident P, permuted K, TRUE-ordered V) ===================
// Inputs q,k,v already tf32-rounded. Output rounded to tf32 for the O-projection.
#define FKTS 72
#define FKE  36
#define FVTS 577
#define FOFF_V 9216
#define FLASH_SMEM_BYTES ((9216 + 9248) * 4)   // 73856 B

__global__ __launch_bounds__(256, 1)
void flash_fwd(const float* __restrict__ Qg, const float* __restrict__ Kg,
               const float* __restrict__ Vg, float* __restrict__ Og)
{
    extern __shared__ float smf[];
    float* Kf = smf;
    float* Vf = smf + FOFF_V;

    const int tid  = threadIdx.x;
    const int wid  = tid >> 5;
    const int lane = tid & 31;
    const int g4 = lane >> 2, tig = lane & 3;
    const int qt = (int)(gridDim.x - 1 - blockIdx.x);   // heavy CTAs first
    const int bh = blockIdx.y;
    const int m0 = qt * 128;
    const int warpRow = m0 + wid * 16;
    const size_t base = (size_t)bh * SEQ * HDIM;
    const float scale = 0.08838834764831845f;

    // ---- Q a-fragments in registers (scale folded, re-rounded) ----
    uint32_t qa[16][4];
    {
        const float* qA = Qg + base + (size_t)(warpRow + g4) * HDIM;
        const float* qB = qA + 8 * HDIM;
#pragma unroll
        for (int kt = 0; kt < 16; kt++) {
            qa[kt][0] = __float_as_uint(to_tf32(qA[kt * 8 + tig] * scale));
            qa[kt][1] = __float_as_uint(to_tf32(qB[kt * 8 + tig] * scale));
            qa[kt][2] = __float_as_uint(to_tf32(qA[kt * 8 + tig + 4] * scale));
            qa[kt][3] = __float_as_uint(to_tf32(qB[kt * 8 + tig + 4] * scale));
        }
    }

    float o[16][4];
#pragma unroll
    for (int nt = 0; nt < 16; nt++)
#pragma unroll
        for (int e = 0; e < 4; e++) o[nt][e] = 0.f;
    float mA = -1e30f, mB = -1e30f, lA = 0.f, lB = 0.f;

    const int ntiles = 2 * qt + 2;
    for (int t = 0; t < ntiles; t++) {
        const int n0 = t * 64;
        __syncthreads();

        // ---- fill K (permuted n) and V (true k order); no conversion needed ----
#pragma unroll
        for (int i = 0; i < 8; i++) {
            int row = i * 8 + wid;
            int gt = row & 7;
            int gp = (gt < 4) ? 2 * gt : 2 * (gt - 4) + 1;
            {
                float4 kv = *(const float4*)(Kg + base + (size_t)(n0 + row) * HDIM + lane * 4);
                int ntg = row >> 3, kt = lane >> 1, kh = lane & 1;
                *(float4*)&Kf[(ntg * 16 + kt) * FKTS + kh * FKE + gp * 4] = kv;
            }
            {
                float4 vv = *(const float4*)(Vg + base + (size_t)(n0 + row) * HDIM + lane * 4);
                int ktv = row >> 3, ev = gt >> 2, q4 = gt & 3;
                float vj[4] = {vv.x, vv.y, vv.z, vv.w};
#pragma unroll
                for (int j = 0; j < 4; j++) {
                    int n = 4 * lane + j;
                    Vf[(n >> 3) * FVTS + ktv * FKTS + ev * FKE + (n & 7) * 4 + q4] = vj[j];
                }
            }
        }
        __syncthreads();

        if (n0 > warpRow + 15) continue;

        // ---- S = Q K^T ----
        float s[8][4];
#pragma unroll
        for (int nt = 0; nt < 8; nt++)
#pragma unroll
            for (int e = 0; e < 4; e++) s[nt][e] = 0.f;
#pragma unroll
        for (int kt = 0; kt < 16; kt++) {
            uint32_t b[8][2];
#pragma unroll
            for (int nt = 0; nt < 8; nt++) {
                b[nt][0] = __float_as_uint(Kf[(nt * 16 + kt) * FKTS + lane]);
                b[nt][1] = __float_as_uint(Kf[(nt * 16 + kt) * FKTS + FKE + lane]);
            }
#pragma unroll
            for (int nt = 0; nt < 8; nt++)
                mma_tf32(s[nt], qa[kt], b[nt]);
        }

        // ---- causal mask ----
        const int qrA = warpRow + g4, qrB = qrA + 8;
        if (n0 + 63 > warpRow) {
#pragma unroll
            for (int nt = 0; nt < 8; nt++) {
                int kv0 = n0 + nt * 8 + tig, kv1 = kv0 + 4;
                if (kv0 > qrA) s[nt][0] = -1e30f;
                if (kv1 > qrA) s[nt][1] = -1e30f;
                if (kv0 > qrB) s[nt][2] = -1e30f;
                if (kv1 > qrB) s[nt][3] = -1e30f;
            }
        }

        // ---- online softmax ----
        float mxA = -1e30f, mxB = -1e30f;
#pragma unroll
        for (int nt = 0; nt < 8; nt++) {
            mxA = fmaxf(mxA, fmaxf(s[nt][0], s[nt][1]));
            mxB = fmaxf(mxB, fmaxf(s[nt][2], s[nt][3]));
        }
        mxA = fmaxf(mxA, __shfl_xor_sync(0xFFFFFFFFu, mxA, 1));
        mxA = fmaxf(mxA, __shfl_xor_sync(0xFFFFFFFFu, mxA, 2));
        mxB = fmaxf(mxB, __shfl_xor_sync(0xFFFFFFFFu, mxB, 1));
        mxB = fmaxf(mxB, __shfl_xor_sync(0xFFFFFFFFu, mxB, 2));
        float mnA = fmaxf(mA, mxA), mnB = fmaxf(mB, mxB);
        float aAl = __expf(mA - mnA), aBl = __expf(mB - mnB);
        mA = mnA; mB = mnB;
#pragma unroll
        for (int nt = 0; nt < 16; nt++) {
            o[nt][0] *= aAl; o[nt][1] *= aAl;
            o[nt][2] *= aBl; o[nt][3] *= aBl;
        }
        float sumA = 0.f, sumB = 0.f;
#pragma unroll
        for (int nt = 0; nt < 8; nt++) {
            float p0 = to_tf32(__expf(s[nt][0] - mA));
            float p1 = to_tf32(__expf(s[nt][1] - mA));
            float p2 = to_tf32(__expf(s[nt][2] - mB));
            float p3 = to_tf32(__expf(s[nt][3] - mB));
            s[nt][0] = p0; s[nt][1] = p1; s[nt][2] = p2; s[nt][3] = p3;
            sumA += p0 + p1; sumB += p2 + p3;
        }
        lA = lA * aAl + sumA;
        lB = lB * aBl + sumB;

        // ---- O += P V ----
#pragma unroll
        for (int kp = 0; kp < 8; kp++) {
            uint32_t a[4] = { __float_as_uint(s[kp][0]), __float_as_uint(s[kp][2]),
                              __float_as_uint(s[kp][1]), __float_as_uint(s[kp][3]) };
            uint32_t b[16][2];
#pragma unroll
            for (int nt = 0; nt < 16; nt++) {
                b[nt][0] = __float_as_uint(Vf[nt * FVTS + kp * FKTS + lane]);
                b[nt][1] = __float_as_uint(Vf[nt * FVTS + kp * FKTS + FKE + lane]);
            }
#pragma unroll
            for (int nt = 0; nt < 16; nt++)
                mma_tf32(o[nt], a, b[nt]);
        }
    }

    // ---- epilogue (round to tf32 for the O-projection) ----
    lA += __shfl_xor_sync(0xFFFFFFFFu, lA, 1);
    lA += __shfl_xor_sync(0xFFFFFFFFu, lA, 2);
    lB += __shfl_xor_sync(0xFFFFFFFFu, lB, 1);
    lB += __shfl_xor_sync(0xFFFFFFFFu, lB, 2);
    float invA = 1.f / lA, invB = 1.f / lB;
    const int b_ = bh >> 4, h = bh & 15;
    const int srA = warpRow + g4, srB = srA + 8;
    float* opA = Og + ((size_t)(b_ * SEQ + srA)) * DMODEL + h * HDIM;
    float* opB = Og + ((size_t)(b_ * SEQ + srB)) * DMODEL + h * HDIM;
#pragma unroll
    for (int nt = 0; nt < 16; nt++) {
        *(float2*)(opA + nt * 8 + 2 * tig) =
            make_float2(to_tf32(o[nt][0] * invA), to_tf32(o[nt][1] * invA));
        *(float2*)(opB + nt * 8 + 2 * tig) =
            make_float2(to_tf32(o[nt][2] * invB), to_tf32(o[nt][3] * invB));
    }
}

// =================== launch ===================
extern "C" void kernel_launch(void* const* d_in, const int* in_sizes, int n_in,
                              void* d_out, int out_size)
{
    (void)in_sizes; (void)n_in; (void)out_size;
    const float* hidden = (const float*)d_in[0];
    const float* Wq = (const float*)d_in[3];
    const float* Wk = (const float*)d_in[4];
    const float* Wv = (const float*)d_in[5];
    const float* Wo = (const float*)d_in[6];
    float* out = (float*)d_out;

    float *q, *k, *v, *attn, *ht, *wq, *wk, *wv, *wo;
    cudaGetSymbolAddress((void**)&q,    g_q);
    cudaGetSymbolAddress((void**)&k,    g_k);
    cudaGetSymbolAddress((void**)&v,    g_v);
    cudaGetSymbolAddress((void**)&attn, g_attn);
    cudaGetSymbolAddress((void**)&ht,   g_ht);
    cudaGetSymbolAddress((void**)&wq,   g_wq);
    cudaGetSymbolAddress((void**)&wk,   g_wk);
    cudaGetSymbolAddress((void**)&wv,   g_wv);
    cudaGetSymbolAddress((void**)&wo,   g_wo);

    cudaFuncSetAttribute(flash_fwd, cudaFuncAttributeMaxDynamicSharedMemorySize,
                         FLASH_SMEM_BYTES);
    cudaFuncSetAttribute(tf32_gemm, cudaFuncAttributeMaxDynamicSharedMemorySize,
                         GEMM_SMEM_BYTES);

    rope_cache_kernel<<<(SEQ * 64 + 255) / 256, 256>>>();

    // pre-round operands to tf32
    const int HN4 = MROWS * DMODEL / 4;
    const int WN4 = DMODEL * DMODEL / 4;
    cvt_tf32_kernel<<<(HN4 + 255) / 256, 256>>>((const float4*)hidden, (float4*)ht, HN4);
    cvt_tf32_kernel<<<(WN4 + 255) / 256, 256>>>((const float4*)Wq, (float4*)wq, WN4);
    cvt_tf32_kernel<<<(WN4 + 255) / 256, 256>>>((const float4*)Wk, (float4*)wk, WN4);
    cvt_tf32_kernel<<<(WN4 + 255) / 256, 256>>>((const float4*)Wv, (float4*)wv, WN4);
    cvt_tf32_kernel<<<(WN4 + 255) / 256, 256>>>((const float4*)Wo, (float4*)wo, WN4);

    dim3 gQKV(DMODEL / 128, MROWS / 128, 3);
    tf32_gemm<<<gQKV, 256, GEMM_SMEM_BYTES>>>(ht, wq, wk, wv, q, k, v, 1);

    rope_apply_kernel<<<(BH * SEQ * 64 + 255) / 256, 256>>>();

    flash_fwd<<<dim3(SEQ / 128, BH), 256, FLASH_SMEM_BYTES>>>(q, k, v, attn);

    dim3 gO(DMODEL / 128, MROWS / 128, 1);
    tf32_gemm<<<gO, 256, GEMM_SMEM_BYTES>>>(attn, wo, wo, wo, out, out, out, 0);
}

// round 13
// speedup vs baseline: 1.2824x; 1.2824x over previous
#include <cuda_runtime.h>
#include <math.h>
#include <stdint.h>

#define BSZ    2
#define SEQ    2048
#define DMODEL 2048
#define NHEADS 16
#define HDIM   128
#define BH     (BSZ*NHEADS)
#define MROWS  (BSZ*SEQ)

// ---- scratch ----
__device__ float g_q[BH*SEQ*HDIM];
__device__ float g_k[BH*SEQ*HDIM];
__device__ float g_v[BH*SEQ*HDIM];
__device__ float g_attn[MROWS*DMODEL];
__device__ float g_cos[SEQ*64];
__device__ float g_sin[SEQ*64];

__device__ __forceinline__ float to_tf32(float x) {
    float y;
    asm("cvt.rna.tf32.f32 %0, %1;" : "=f"(y) : "f"(x));
    return y;
}
__device__ __forceinline__ void mma_tf32(float* c, const uint32_t* a, const uint32_t* b) {
    asm volatile(
        "mma.sync.aligned.m16n8k8.row.col.f32.tf32.tf32.f32 "
        "{%0,%1,%2,%3}, {%4,%5,%6,%7}, {%8,%9}, {%0,%1,%2,%3};"
        : "+f"(c[0]), "+f"(c[1]), "+f"(c[2]), "+f"(c[3])
        : "r"(a[0]), "r"(a[1]), "r"(a[2]), "r"(a[3]), "r"(b[0]), "r"(b[1]));
}
__device__ __forceinline__ float4 tf32x4(float4 v) {
    v.x = to_tf32(v.x); v.y = to_tf32(v.y); v.z = to_tf32(v.z); v.w = to_tf32(v.w);
    return v;
}

// =================== RoPE ===================
__global__ void rope_cache_kernel() {
    int idx = blockIdx.x * blockDim.x + threadIdx.x;
    if (idx >= SEQ * 64) return;
    int pos = idx >> 6, j = idx & 63;
    double e    = (double)(2 * j) / 128.0;
    double invf = pow(10000.0, -e);
    double ang  = (double)pos * invf;
    g_cos[idx] = (float)cos(ang);
    g_sin[idx] = (float)sin(ang);
}
__global__ void rope_apply_kernel() {
    int idx = blockIdx.x * blockDim.x + threadIdx.x;
    if (idx >= BH * SEQ * 64) return;
    int j = idx & 63, row = idx >> 6, s = row & (SEQ - 1);
    float c = g_cos[s * 64 + j], sn = g_sin[s * 64 + j];
    float* qp = g_q + (size_t)row * HDIM;
    float* kp = g_k + (size_t)row * HDIM;
    float q1 = qp[j], q2 = qp[j + 64];
    qp[j] = q1 * c - q2 * sn;  qp[j + 64] = q2 * c + q1 * sn;
    float k1 = kp[j], k2 = kp[j + 64];
    kp[j] = k1 * c - k2 * sn;  kp[j + 64] = k2 * c + k1 * sn;
}

// =================== TF32 GEMM: vector-fragment smem, double-buffered ===================
// C[m,n] = sum_k A[m,k]*B[n,k]. 128x128 CTA tile, K stage 16, 8 warps (2m x 4n).
// A vector a-frag layout: tile (mt*2+kb), stride 132 words:
//   element (r_local, k8) at word tile*132 + 4*(4g + (tig ^ ((g>>1)&3))) + (hi + 2*kh)
//   where g=r&7, hi=(r>>3)&1, tig=k8&3, kh=k8>>2.
//   consumer: LDS.128 at tile*132 + 4*swzL,  swzL = lane ^ ((lane>>3)&3)  (conflict-free)
// B pair b-frag layout: tile (nt*2+kb), stride 66 words:
//   element (n_local, k8) at word tile*66 + 2*(4g + (j ^ ((g>>1)&3))) + (k8>>2)
//   consumer: LDS.64 at tile*66 + 2*swzL (conflict-free)
#define GEMM_K  DMODEL
#define KSTAGES (GEMM_K / 16)    // 128
#define ATS 132
#define BTS 66
#define A_STAGE (16*ATS)         // 2112 words
#define B_STAGE (32*BTS)         // 2112 words

__global__ __launch_bounds__(256, 2)
void tf32_gemm(const float* __restrict__ A,
               const float* __restrict__ B0, const float* __restrict__ B1,
               const float* __restrict__ B2,
               float* __restrict__ C0, float* __restrict__ C1, float* __restrict__ C2,
               int mode)
{
    __shared__ float As[2][A_STAGE];
    __shared__ float Bs[2][B_STAGE];

    const int z = blockIdx.z;
    const float* B = (z == 0) ? B0 : (z == 1) ? B1 : B2;
    float* C       = (z == 0) ? C0 : (z == 1) ? C1 : C2;

    const int tid  = threadIdx.x;
    const int wid  = tid >> 5;
    const int lane = tid & 31;
    const int bm = blockIdx.y * 128;
    const int bn = blockIdx.x * 128;
    const int wm = wid >> 2;
    const int wn = wid & 3;
    const int swzL = lane ^ ((lane >> 3) & 3);

    // fill mapping: 2 float4 chunks per operand per thread per stage
    int aWord[2], bWord[2], cSw[2];
    const float4* Ap[2];
    const float4* Bp[2];
#pragma unroll
    for (int i = 0; i < 2; i++) {
        int f = i * 256 + tid;
        int row = f >> 2, c4 = f & 3;
        int kb = c4 >> 1, kh = c4 & 1;
        int g = row & 7, hi = (row >> 3) & 1;
        int mt = row >> 4, nt = row >> 3;
        cSw[i] = (g >> 1) & 3;
        aWord[i] = (mt * 2 + kb) * ATS + 16 * g + (hi + 2 * kh);
        bWord[i] = (nt * 2 + kb) * BTS + 8 * g + kh;
        Ap[i] = (const float4*)(A + (size_t)(bm + row) * GEMM_K) + c4;
        Bp[i] = (const float4*)(B + (size_t)(bn + row) * GEMM_K) + c4;
    }

    float acc[4][4][4];
#pragma unroll
    for (int mt = 0; mt < 4; mt++)
#pragma unroll
        for (int nt = 0; nt < 4; nt++)
#pragma unroll
            for (int e = 0; e < 4; e++) acc[mt][nt][e] = 0.f;

    float4 pa[2], pb[2];
#pragma unroll
    for (int i = 0; i < 2; i++) { pa[i] = Ap[i][0]; pb[i] = Bp[i][0]; }
#pragma unroll
    for (int i = 0; i < 2; i++) {
        float4 a = tf32x4(pa[i]), b = tf32x4(pb[i]);
        float va[4] = {a.x, a.y, a.z, a.w};
        float vb[4] = {b.x, b.y, b.z, b.w};
#pragma unroll
        for (int j = 0; j < 4; j++) {
            As[0][aWord[i] + 4 * (j ^ cSw[i])] = va[j];
            Bs[0][bWord[i] + 2 * (j ^ cSw[i])] = vb[j];
        }
    }
#pragma unroll
    for (int i = 0; i < 2; i++) { pa[i] = Ap[i][4]; pb[i] = Bp[i][4]; }
    __syncthreads();

    const int aT0 = (wm * 4) * 2 * ATS + 4 * swzL;
    const int bT0 = (wn * 4) * 2 * BTS + 2 * swzL;

#pragma unroll 1
    for (int ks = 0; ks < KSTAGES; ks++) {
        const int buf = ks & 1;
        if (ks + 1 < KSTAGES) {
#pragma unroll
            for (int i = 0; i < 2; i++) {
                float4 a = tf32x4(pa[i]), b = tf32x4(pb[i]);
                float va[4] = {a.x, a.y, a.z, a.w};
                float vb[4] = {b.x, b.y, b.z, b.w};
#pragma unroll
                for (int j = 0; j < 4; j++) {
                    As[buf ^ 1][aWord[i] + 4 * (j ^ cSw[i])] = va[j];
                    Bs[buf ^ 1][bWord[i] + 2 * (j ^ cSw[i])] = vb[j];
                }
            }
        }
#pragma unroll
        for (int kb = 0; kb < 2; kb++) {
            uint32_t a[4][4], b[4][2];
#pragma unroll
            for (int mt = 0; mt < 4; mt++)
                *(uint4*)a[mt] = *(const uint4*)&As[buf][aT0 + (mt * 2 + kb) * ATS];
#pragma unroll
            for (int nt = 0; nt < 4; nt++)
                *(uint2*)b[nt] = *(const uint2*)&Bs[buf][bT0 + (nt * 2 + kb) * BTS];
#pragma unroll
            for (int mt = 0; mt < 4; mt++)
#pragma unroll
                for (int nt = 0; nt < 4; nt++)
                    mma_tf32(acc[mt][nt], a[mt], b[nt]);
        }
        if (ks + 2 < KSTAGES) {
#pragma unroll
            for (int i = 0; i < 2; i++) {
                pa[i] = Ap[i][(ks + 2) * 4];
                pb[i] = Bp[i][(ks + 2) * 4];
            }
        }
        __syncthreads();
    }

    const int g = lane >> 2, tig = lane & 3;
#pragma unroll
    for (int mt = 0; mt < 4; mt++) {
#pragma unroll
        for (int nt = 0; nt < 4; nt++) {
            int row = bm + wm * 64 + mt * 16 + g;
            int col = bn + wn * 32 + nt * 8 + tig * 2;
            float* c0;
            size_t rstride;
            if (mode == 0) {
                c0 = C + (size_t)row * DMODEL + col;
                rstride = DMODEL;
            } else {
                int b = row >> 11, s = row & (SEQ - 1);
                int h = col >> 7, hd = col & 127;
                c0 = C + (((size_t)(b * NHEADS + h)) * SEQ + s) * HDIM + hd;
                rstride = HDIM;
            }
            *(float2*)c0 = make_float2(acc[mt][nt][0], acc[mt][nt][1]);
            *(float2*)(c0 + 8 * rstride) = make_float2(acc[mt][nt][2], acc[mt][nt][3]);
        }
    }
}

// =================== Flash attention (register-resident P, permuted K, TRUE-ordered V) ===================
#define FKTS 72
#define FKE  36
#define FVTS 577
#define FOFF_V 9216
#define FLASH_SMEM_BYTES ((9216 + 9248) * 4)   // 73856 B

__global__ __launch_bounds__(256, 1)
void flash_fwd(const float* __restrict__ Qg, const float* __restrict__ Kg,
               const float* __restrict__ Vg, float* __restrict__ Og)
{
    extern __shared__ float smf[];
    float* Kf = smf;
    float* Vf = smf + FOFF_V;

    const int tid  = threadIdx.x;
    const int wid  = tid >> 5;
    const int lane = tid & 31;
    const int g4 = lane >> 2, tig = lane & 3;
    const int qt = (int)(gridDim.x - 1 - blockIdx.x);   // heavy CTAs first
    const int bh = blockIdx.y;
    const int m0 = qt * 128;
    const int warpRow = m0 + wid * 16;
    const size_t base = (size_t)bh * SEQ * HDIM;
    const float scale = 0.08838834764831845f;

    // ---- Q a-fragments in registers (scale folded in) ----
    uint32_t qa[16][4];
    {
        const float* qA = Qg + base + (size_t)(warpRow + g4) * HDIM;
        const float* qB = qA + 8 * HDIM;
#pragma unroll
        for (int kt = 0; kt < 16; kt++) {
            qa[kt][0] = __float_as_uint(to_tf32(qA[kt * 8 + tig] * scale));
            qa[kt][1] = __float_as_uint(to_tf32(qB[kt * 8 + tig] * scale));
            qa[kt][2] = __float_as_uint(to_tf32(qA[kt * 8 + tig + 4] * scale));
            qa[kt][3] = __float_as_uint(to_tf32(qB[kt * 8 + tig + 4] * scale));
        }
    }

    float o[16][4];
#pragma unroll
    for (int nt = 0; nt < 16; nt++)
#pragma unroll
        for (int e = 0; e < 4; e++) o[nt][e] = 0.f;
    float mA = -1e30f, mB = -1e30f, lA = 0.f, lB = 0.f;

    const int ntiles = 2 * qt + 2;
    for (int t = 0; t < ntiles; t++) {
        const int n0 = t * 64;
        __syncthreads();

        // ---- fill K (permuted n) and V (true k order) ----
#pragma unroll
        for (int i = 0; i < 8; i++) {
            int row = i * 8 + wid;
            int gt = row & 7;
            int gp = (gt < 4) ? 2 * gt : 2 * (gt - 4) + 1;
            {
                float4 kv = tf32x4(*(const float4*)(Kg + base + (size_t)(n0 + row) * HDIM + lane * 4));
                int ntg = row >> 3, kt = lane >> 1, kh = lane & 1;
                *(float4*)&Kf[(ntg * 16 + kt) * FKTS + kh * FKE + gp * 4] = kv;
            }
            {
                float4 vv = tf32x4(*(const float4*)(Vg + base + (size_t)(n0 + row) * HDIM + lane * 4));
                int ktv = row >> 3, ev = gt >> 2, q4 = gt & 3;
                float vj[4] = {vv.x, vv.y, vv.z, vv.w};
#pragma unroll
                for (int j = 0; j < 4; j++) {
                    int n = 4 * lane + j;
                    Vf[(n >> 3) * FVTS + ktv * FKTS + ev * FKE + (n & 7) * 4 + q4] = vj[j];
                }
            }
        }
        __syncthreads();

        if (n0 > warpRow + 15) continue;

        // ---- S = Q K^T ----
        float s[8][4];
#pragma unroll
        for (int nt = 0; nt < 8; nt++)
#pragma unroll
            for (int e = 0; e < 4; e++) s[nt][e] = 0.f;
#pragma unroll
        for (int kt = 0; kt < 16; kt++) {
            uint32_t b[8][2];
#pragma unroll
            for (int nt = 0; nt < 8; nt++) {
                b[nt][0] = __float_as_uint(Kf[(nt * 16 + kt) * FKTS + lane]);
                b[nt][1] = __float_as_uint(Kf[(nt * 16 + kt) * FKTS + FKE + lane]);
            }
#pragma unroll
            for (int nt = 0; nt < 8; nt++)
                mma_tf32(s[nt], qa[kt], b[nt]);
        }

        // ---- causal mask ----
        const int qrA = warpRow + g4, qrB = qrA + 8;
        if (n0 + 63 > warpRow) {
#pragma unroll
            for (int nt = 0; nt < 8; nt++) {
                int kv0 = n0 + nt * 8 + tig, kv1 = kv0 + 4;
                if (kv0 > qrA) s[nt][0] = -1e30f;
                if (kv1 > qrA) s[nt][1] = -1e30f;
                if (kv0 > qrB) s[nt][2] = -1e30f;
                if (kv1 > qrB) s[nt][3] = -1e30f;
            }
        }

        // ---- online softmax ----
        float mxA = -1e30f, mxB = -1e30f;
#pragma unroll
        for (int nt = 0; nt < 8; nt++) {
            mxA = fmaxf(mxA, fmaxf(s[nt][0], s[nt][1]));
            mxB = fmaxf(mxB, fmaxf(s[nt][2], s[nt][3]));
        }
        mxA = fmaxf(mxA, __shfl_xor_sync(0xFFFFFFFFu, mxA, 1));
        mxA = fmaxf(mxA, __shfl_xor_sync(0xFFFFFFFFu, mxA, 2));
        mxB = fmaxf(mxB, __shfl_xor_sync(0xFFFFFFFFu, mxB, 1));
        mxB = fmaxf(mxB, __shfl_xor_sync(0xFFFFFFFFu, mxB, 2));
        float mnA = fmaxf(mA, mxA), mnB = fmaxf(mB, mxB);
        float aAl = __expf(mA - mnA), aBl = __expf(mB - mnB);
        mA = mnA; mB = mnB;
#pragma unroll
        for (int nt = 0; nt < 16; nt++) {
            o[nt][0] *= aAl; o[nt][1] *= aAl;
            o[nt][2] *= aBl; o[nt][3] *= aBl;
        }
        float sumA = 0.f, sumB = 0.f;
#pragma unroll
        for (int nt = 0; nt < 8; nt++) {
            float p0 = to_tf32(__expf(s[nt][0] - mA));
            float p1 = to_tf32(__expf(s[nt][1] - mA));
            float p2 = to_tf32(__expf(s[nt][2] - mB));
            float p3 = to_tf32(__expf(s[nt][3] - mB));
            s[nt][0] = p0; s[nt][1] = p1; s[nt][2] = p2; s[nt][3] = p3;
            sumA += p0 + p1; sumB += p2 + p3;
        }
        lA = lA * aAl + sumA;
        lB = lB * aBl + sumB;

        // ---- O += P V  (P a-frag = {s0, s2, s1, s3}) ----
#pragma unroll
        for (int kp = 0; kp < 8; kp++) {
            uint32_t a[4] = { __float_as_uint(s[kp][0]), __float_as_uint(s[kp][2]),
                              __float_as_uint(s[kp][1]), __float_as_uint(s[kp][3]) };
            uint32_t b[16][2];
#pragma unroll
            for (int nt = 0; nt < 16; nt++) {
                b[nt][0] = __float_as_uint(Vf[nt * FVTS + kp * FKTS + lane]);
                b[nt][1] = __float_as_uint(Vf[nt * FVTS + kp * FKTS + FKE + lane]);
            }
#pragma unroll
            for (int nt = 0; nt < 16; nt++)
                mma_tf32(o[nt], a, b[nt]);
        }
    }

    // ---- epilogue ----
    lA += __shfl_xor_sync(0xFFFFFFFFu, lA, 1);
    lA += __shfl_xor_sync(0xFFFFFFFFu, lA, 2);
    lB += __shfl_xor_sync(0xFFFFFFFFu, lB, 1);
    lB += __shfl_xor_sync(0xFFFFFFFFu, lB, 2);
    float invA = 1.f / lA, invB = 1.f / lB;
    const int b_ = bh >> 4, h = bh & 15;
    const int srA = warpRow + g4, srB = srA + 8;
    float* opA = Og + ((size_t)(b_ * SEQ + srA)) * DMODEL + h * HDIM;
    float* opB = Og + ((size_t)(b_ * SEQ + srB)) * DMODEL + h * HDIM;
#pragma unroll
    for (int nt = 0; nt < 16; nt++) {
        *(float2*)(opA + nt * 8 + 2 * tig) = make_float2(o[nt][0] * invA, o[nt][1] * invA);
        *(float2*)(opB + nt * 8 + 2 * tig) = make_float2(o[nt][2] * invB, o[nt][3] * invB);
    }
}

// =================== launch ===================
extern "C" void kernel_launch(void* const* d_in, const int* in_sizes, int n_in,
                              void* d_out, int out_size)
{
    (void)in_sizes; (void)n_in; (void)out_size;
    const float* hidden = (const float*)d_in[0];
    const float* Wq = (const float*)d_in[3];
    const float* Wk = (const float*)d_in[4];
    const float* Wv = (const float*)d_in[5];
    const float* Wo = (const float*)d_in[6];
    float* out = (float*)d_out;

    float *q, *k, *v, *attn;
    cudaGetSymbolAddress((void**)&q,    g_q);
    cudaGetSymbolAddress((void**)&k,    g_k);
    cudaGetSymbolAddress((void**)&v,    g_v);
    cudaGetSymbolAddress((void**)&attn, g_attn);

    cudaFuncSetAttribute(flash_fwd, cudaFuncAttributeMaxDynamicSharedMemorySize,
                         FLASH_SMEM_BYTES);

    rope_cache_kernel<<<(SEQ * 64 + 255) / 256, 256>>>();

    dim3 gQKV(DMODEL / 128, MROWS / 128, 3);
    tf32_gemm<<<gQKV, 256>>>(hidden, Wq, Wk, Wv, q, k, v, 1);

    rope_apply_kernel<<<(BH * SEQ * 64 + 255) / 256, 256>>>();

    flash_fwd<<<dim3(SEQ / 128, BH), 256, FLASH_SMEM_BYTES>>>(q, k, v, attn);

    dim3 gO(DMODEL / 128, MROWS / 128, 1);
    tf32_gemm<<<gO, 256>>>(attn, Wo, Wo, Wo, out, out, out, 0);
}

// round 14
// speedup vs baseline: 1.2921x; 1.0076x over previous
#include <cuda_runtime.h>
#include <math.h>
#include <stdint.h>

#define BSZ    2
#define SEQ    2048
#define DMODEL 2048
#define NHEADS 16
#define HDIM   128
#define BH     (BSZ*NHEADS)
#define MROWS  (BSZ*SEQ)

// ---- scratch ----
__device__ float g_q[BH*SEQ*HDIM];
__device__ float g_k[BH*SEQ*HDIM];
__device__ float g_v[BH*SEQ*HDIM];
__device__ float g_attn[MROWS*DMODEL];
__device__ float g_cos[SEQ*64];
__device__ float g_sin[SEQ*64];

__device__ __forceinline__ float to_tf32(float x) {
    float y;
    asm("cvt.rna.tf32.f32 %0, %1;" : "=f"(y) : "f"(x));
    return y;
}
__device__ __forceinline__ void mma_tf32(float* c, const uint32_t* a, const uint32_t* b) {
    asm volatile(
        "mma.sync.aligned.m16n8k8.row.col.f32.tf32.tf32.f32 "
        "{%0,%1,%2,%3}, {%4,%5,%6,%7}, {%8,%9}, {%0,%1,%2,%3};"
        : "+f"(c[0]), "+f"(c[1]), "+f"(c[2]), "+f"(c[3])
        : "r"(a[0]), "r"(a[1]), "r"(a[2]), "r"(a[3]), "r"(b[0]), "r"(b[1]));
}
__device__ __forceinline__ float4 tf32x4(float4 v) {
    v.x = to_tf32(v.x); v.y = to_tf32(v.y); v.z = to_tf32(v.z); v.w = to_tf32(v.w);
    return v;
}

// =================== RoPE ===================
__global__ void rope_cache_kernel() {
    int idx = blockIdx.x * blockDim.x + threadIdx.x;
    if (idx >= SEQ * 64) return;
    int pos = idx >> 6, j = idx & 63;
    double e    = (double)(2 * j) / 128.0;
    double invf = pow(10000.0, -e);
    double ang  = (double)pos * invf;
    g_cos[idx] = (float)cos(ang);
    g_sin[idx] = (float)sin(ang);
}
__global__ void rope_apply_kernel() {
    int idx = blockIdx.x * blockDim.x + threadIdx.x;
    if (idx >= BH * SEQ * 64) return;
    int j = idx & 63, row = idx >> 6, s = row & (SEQ - 1);
    float c = g_cos[s * 64 + j], sn = g_sin[s * 64 + j];
    float* qp = g_q + (size_t)row * HDIM;
    float* kp = g_k + (size_t)row * HDIM;
    float q1 = qp[j], q2 = qp[j + 64];
    qp[j] = q1 * c - q2 * sn;  qp[j + 64] = q2 * c + q1 * sn;
    float k1 = kp[j], k2 = kp[j + 64];
    kp[j] = k1 * c - k2 * sn;  kp[j + 64] = k2 * c + k1 * sn;
}

// =================== TF32 GEMM: vector-fragment smem, double-buffered (R12, best) ===================
#define GEMM_K  DMODEL
#define KSTAGES (GEMM_K / 16)    // 128
#define ATS 132
#define BTS 66
#define A_STAGE (16*ATS)         // 2112 words
#define B_STAGE (32*BTS)         // 2112 words

__global__ __launch_bounds__(256, 2)
void tf32_gemm(const float* __restrict__ A,
               const float* __restrict__ B0, const float* __restrict__ B1,
               const float* __restrict__ B2,
               float* __restrict__ C0, float* __restrict__ C1, float* __restrict__ C2,
               int mode)
{
    __shared__ float As[2][A_STAGE];
    __shared__ float Bs[2][B_STAGE];

    const int z = blockIdx.z;
    const float* B = (z == 0) ? B0 : (z == 1) ? B1 : B2;
    float* C       = (z == 0) ? C0 : (z == 1) ? C1 : C2;

    const int tid  = threadIdx.x;
    const int wid  = tid >> 5;
    const int lane = tid & 31;
    const int bm = blockIdx.y * 128;
    const int bn = blockIdx.x * 128;
    const int wm = wid >> 2;
    const int wn = wid & 3;
    const int swzL = lane ^ ((lane >> 3) & 3);

    int aWord[2], bWord[2], cSw[2];
    const float4* Ap[2];
    const float4* Bp[2];
#pragma unroll
    for (int i = 0; i < 2; i++) {
        int f = i * 256 + tid;
        int row = f >> 2, c4 = f & 3;
        int kb = c4 >> 1, kh = c4 & 1;
        int g = row & 7, hi = (row >> 3) & 1;
        int mt = row >> 4, nt = row >> 3;
        cSw[i] = (g >> 1) & 3;
        aWord[i] = (mt * 2 + kb) * ATS + 16 * g + (hi + 2 * kh);
        bWord[i] = (nt * 2 + kb) * BTS + 8 * g + kh;
        Ap[i] = (const float4*)(A + (size_t)(bm + row) * GEMM_K) + c4;
        Bp[i] = (const float4*)(B + (size_t)(bn + row) * GEMM_K) + c4;
    }

    float acc[4][4][4];
#pragma unroll
    for (int mt = 0; mt < 4; mt++)
#pragma unroll
        for (int nt = 0; nt < 4; nt++)
#pragma unroll
            for (int e = 0; e < 4; e++) acc[mt][nt][e] = 0.f;

    float4 pa[2], pb[2];
#pragma unroll
    for (int i = 0; i < 2; i++) { pa[i] = Ap[i][0]; pb[i] = Bp[i][0]; }
#pragma unroll
    for (int i = 0; i < 2; i++) {
        float4 a = tf32x4(pa[i]), b = tf32x4(pb[i]);
        float va[4] = {a.x, a.y, a.z, a.w};
        float vb[4] = {b.x, b.y, b.z, b.w};
#pragma unroll
        for (int j = 0; j < 4; j++) {
            As[0][aWord[i] + 4 * (j ^ cSw[i])] = va[j];
            Bs[0][bWord[i] + 2 * (j ^ cSw[i])] = vb[j];
        }
    }
#pragma unroll
    for (int i = 0; i < 2; i++) { pa[i] = Ap[i][4]; pb[i] = Bp[i][4]; }
    __syncthreads();

    const int aT0 = (wm * 4) * 2 * ATS + 4 * swzL;
    const int bT0 = (wn * 4) * 2 * BTS + 2 * swzL;

#pragma unroll 1
    for (int ks = 0; ks < KSTAGES; ks++) {
        const int buf = ks & 1;
        if (ks + 1 < KSTAGES) {
#pragma unroll
            for (int i = 0; i < 2; i++) {
                float4 a = tf32x4(pa[i]), b = tf32x4(pb[i]);
                float va[4] = {a.x, a.y, a.z, a.w};
                float vb[4] = {b.x, b.y, b.z, b.w};
#pragma unroll
                for (int j = 0; j < 4; j++) {
                    As[buf ^ 1][aWord[i] + 4 * (j ^ cSw[i])] = va[j];
                    Bs[buf ^ 1][bWord[i] + 2 * (j ^ cSw[i])] = vb[j];
                }
            }
        }
#pragma unroll
        for (int kb = 0; kb < 2; kb++) {
            uint32_t a[4][4], b[4][2];
#pragma unroll
            for (int mt = 0; mt < 4; mt++)
                *(uint4*)a[mt] = *(const uint4*)&As[buf][aT0 + (mt * 2 + kb) * ATS];
#pragma unroll
            for (int nt = 0; nt < 4; nt++)
                *(uint2*)b[nt] = *(const uint2*)&Bs[buf][bT0 + (nt * 2 + kb) * BTS];
#pragma unroll
            for (int mt = 0; mt < 4; mt++)
#pragma unroll
                for (int nt = 0; nt < 4; nt++)
                    mma_tf32(acc[mt][nt], a[mt], b[nt]);
        }
        if (ks + 2 < KSTAGES) {
#pragma unroll
            for (int i = 0; i < 2; i++) {
                pa[i] = Ap[i][(ks + 2) * 4];
                pb[i] = Bp[i][(ks + 2) * 4];
            }
        }
        __syncthreads();
    }

    const int g = lane >> 2, tig = lane & 3;
#pragma unroll
    for (int mt = 0; mt < 4; mt++) {
#pragma unroll
        for (int nt = 0; nt < 4; nt++) {
            int row = bm + wm * 64 + mt * 16 + g;
            int col = bn + wn * 32 + nt * 8 + tig * 2;
            float* c0;
            size_t rstride;
            if (mode == 0) {
                c0 = C + (size_t)row * DMODEL + col;
                rstride = DMODEL;
            } else {
                int b = row >> 11, s = row & (SEQ - 1);
                int h = col >> 7, hd = col & 127;
                c0 = C + (((size_t)(b * NHEADS + h)) * SEQ + s) * HDIM + hd;
                rstride = HDIM;
            }
            *(float2*)c0 = make_float2(acc[mt][nt][0], acc[mt][nt][1]);
            *(float2*)(c0 + 8 * rstride) = make_float2(acc[mt][nt][2], acc[mt][nt][3]);
        }
    }
}

// =================== Flash attention: 128-thread CTAs, 64-q tiles, 2 CTAs/SM ===================
// Same per-warp math as R8/R12 (register P, permuted K, true-ordered V).
#define FKTS 72
#define FKE  36
#define FVTS 577
#define FOFF_V 9216
#define FLASH_SMEM_BYTES ((9216 + 9248) * 4)   // 73856 B per CTA; 2 CTAs/SM

__global__ __launch_bounds__(128, 2)
void flash_fwd(const float* __restrict__ Qg, const float* __restrict__ Kg,
               const float* __restrict__ Vg, float* __restrict__ Og)
{
    extern __shared__ float smf[];
    float* Kf = smf;
    float* Vf = smf + FOFF_V;

    const int tid  = threadIdx.x;
    const int wid  = tid >> 5;            // 0..3
    const int lane = tid & 31;
    const int g4 = lane >> 2, tig = lane & 3;
    const int qt = (int)(gridDim.x - 1 - blockIdx.x);   // heavy CTAs first
    const int bh = blockIdx.y;
    const int m0 = qt * 64;
    const int warpRow = m0 + wid * 16;
    const size_t base = (size_t)bh * SEQ * HDIM;
    const float scale = 0.08838834764831845f;

    // ---- Q a-fragments in registers (scale folded in) ----
    uint32_t qa[16][4];
    {
        const float* qA = Qg + base + (size_t)(warpRow + g4) * HDIM;
        const float* qB = qA + 8 * HDIM;
#pragma unroll
        for (int kt = 0; kt < 16; kt++) {
            qa[kt][0] = __float_as_uint(to_tf32(qA[kt * 8 + tig] * scale));
            qa[kt][1] = __float_as_uint(to_tf32(qB[kt * 8 + tig] * scale));
            qa[kt][2] = __float_as_uint(to_tf32(qA[kt * 8 + tig + 4] * scale));
            qa[kt][3] = __float_as_uint(to_tf32(qB[kt * 8 + tig + 4] * scale));
        }
    }

    float o[16][4];
#pragma unroll
    for (int nt = 0; nt < 16; nt++)
#pragma unroll
        for (int e = 0; e < 4; e++) o[nt][e] = 0.f;
    float mA = -1e30f, mB = -1e30f, lA = 0.f, lB = 0.f;

    const int ntiles = qt + 1;
    for (int t = 0; t < ntiles; t++) {
        const int n0 = t * 64;
        __syncthreads();

        // ---- fill K (permuted n) and V (true k order): 16 rows-iters x 4 warps ----
#pragma unroll
        for (int i = 0; i < 16; i++) {
            int row = i * 4 + wid;          // warp-uniform kv row 0..63
            int gt = row & 7;
            int gp = (gt < 4) ? 2 * gt : 2 * (gt - 4) + 1;
            {
                float4 kv = tf32x4(*(const float4*)(Kg + base + (size_t)(n0 + row) * HDIM + lane * 4));
                int ntg = row >> 3, kt = lane >> 1, kh = lane & 1;
                *(float4*)&Kf[(ntg * 16 + kt) * FKTS + kh * FKE + gp * 4] = kv;
            }
            {
                float4 vv = tf32x4(*(const float4*)(Vg + base + (size_t)(n0 + row) * HDIM + lane * 4));
                int ktv = row >> 3, ev = gt >> 2, q4 = gt & 3;
                float vj[4] = {vv.x, vv.y, vv.z, vv.w};
#pragma unroll
                for (int j = 0; j < 4; j++) {
                    int n = 4 * lane + j;
                    Vf[(n >> 3) * FVTS + ktv * FKTS + ev * FKE + (n & 7) * 4 + q4] = vj[j];
                }
            }
        }
        __syncthreads();

        // ---- S = Q K^T ----
        float s[8][4];
#pragma unroll
        for (int nt = 0; nt < 8; nt++)
#pragma unroll
            for (int e = 0; e < 4; e++) s[nt][e] = 0.f;
#pragma unroll
        for (int kt = 0; kt < 16; kt++) {
            uint32_t b[8][2];
#pragma unroll
            for (int nt = 0; nt < 8; nt++) {
                b[nt][0] = __float_as_uint(Kf[(nt * 16 + kt) * FKTS + lane]);
                b[nt][1] = __float_as_uint(Kf[(nt * 16 + kt) * FKTS + FKE + lane]);
            }
#pragma unroll
            for (int nt = 0; nt < 8; nt++)
                mma_tf32(s[nt], qa[kt], b[nt]);
        }

        // ---- causal mask (true kv indices) ----
        const int qrA = warpRow + g4, qrB = qrA + 8;
        if (n0 + 63 > warpRow) {
#pragma unroll
            for (int nt = 0; nt < 8; nt++) {
                int kv0 = n0 + nt * 8 + tig, kv1 = kv0 + 4;
                if (kv0 > qrA) s[nt][0] = -1e30f;
                if (kv1 > qrA) s[nt][1] = -1e30f;
                if (kv0 > qrB) s[nt][2] = -1e30f;
                if (kv1 > qrB) s[nt][3] = -1e30f;
            }
        }

        // ---- online softmax ----
        float mxA = -1e30f, mxB = -1e30f;
#pragma unroll
        for (int nt = 0; nt < 8; nt++) {
            mxA = fmaxf(mxA, fmaxf(s[nt][0], s[nt][1]));
            mxB = fmaxf(mxB, fmaxf(s[nt][2], s[nt][3]));
        }
        mxA = fmaxf(mxA, __shfl_xor_sync(0xFFFFFFFFu, mxA, 1));
        mxA = fmaxf(mxA, __shfl_xor_sync(0xFFFFFFFFu, mxA, 2));
        mxB = fmaxf(mxB, __shfl_xor_sync(0xFFFFFFFFu, mxB, 1));
        mxB = fmaxf(mxB, __shfl_xor_sync(0xFFFFFFFFu, mxB, 2));
        float mnA = fmaxf(mA, mxA), mnB = fmaxf(mB, mxB);
        float aAl = __expf(mA - mnA), aBl = __expf(mB - mnB);
        mA = mnA; mB = mnB;
#pragma unroll
        for (int nt = 0; nt < 16; nt++) {
            o[nt][0] *= aAl; o[nt][1] *= aAl;
            o[nt][2] *= aBl; o[nt][3] *= aBl;
        }
        float sumA = 0.f, sumB = 0.f;
#pragma unroll
        for (int nt = 0; nt < 8; nt++) {
            float p0 = to_tf32(__expf(s[nt][0] - mA));
            float p1 = to_tf32(__expf(s[nt][1] - mA));
            float p2 = to_tf32(__expf(s[nt][2] - mB));
            float p3 = to_tf32(__expf(s[nt][3] - mB));
            s[nt][0] = p0; s[nt][1] = p1; s[nt][2] = p2; s[nt][3] = p3;
            sumA += p0 + p1; sumB += p2 + p3;
        }
        lA = lA * aAl + sumA;
        lB = lB * aBl + sumB;

        // ---- O += P V  (P a-frag = {s0, s2, s1, s3}) ----
#pragma unroll
        for (int kp = 0; kp < 8; kp++) {
            uint32_t a[4] = { __float_as_uint(s[kp][0]), __float_as_uint(s[kp][2]),
                              __float_as_uint(s[kp][1]), __float_as_uint(s[kp][3]) };
            uint32_t b[16][2];
#pragma unroll
            for (int nt = 0; nt < 16; nt++) {
                b[nt][0] = __float_as_uint(Vf[nt * FVTS + kp * FKTS + lane]);
                b[nt][1] = __float_as_uint(Vf[nt * FVTS + kp * FKTS + FKE + lane]);
            }
#pragma unroll
            for (int nt = 0; nt < 16; nt++)
                mma_tf32(o[nt], a, b[nt]);
        }
    }

    // ---- epilogue ----
    lA += __shfl_xor_sync(0xFFFFFFFFu, lA, 1);
    lA += __shfl_xor_sync(0xFFFFFFFFu, lA, 2);
    lB += __shfl_xor_sync(0xFFFFFFFFu, lB, 1);
    lB += __shfl_xor_sync(0xFFFFFFFFu, lB, 2);
    float invA = 1.f / lA, invB = 1.f / lB;
    const int b_ = bh >> 4, h = bh & 15;
    const int srA = warpRow + g4, srB = srA + 8;
    float* opA = Og + ((size_t)(b_ * SEQ + srA)) * DMODEL + h * HDIM;
    float* opB = Og + ((size_t)(b_ * SEQ + srB)) * DMODEL + h * HDIM;
#pragma unroll
    for (int nt = 0; nt < 16; nt++) {
        *(float2*)(opA + nt * 8 + 2 * tig) = make_float2(o[nt][0] * invA, o[nt][1] * invA);
        *(float2*)(opB + nt * 8 + 2 * tig) = make_float2(o[nt][2] * invB, o[nt][3] * invB);
    }
}

// =================== launch ===================
extern "C" void kernel_launch(void* const* d_in, const int* in_sizes, int n_in,
                              void* d_out, int out_size)
{
    (void)in_sizes; (void)n_in; (void)out_size;
    const float* hidden = (const float*)d_in[0];
    const float* Wq = (const float*)d_in[3];
    const float* Wk = (const float*)d_in[4];
    const float* Wv = (const float*)d_in[5];
    const float* Wo = (const float*)d_in[6];
    float* out = (float*)d_out;

    float *q, *k, *v, *attn;
    cudaGetSymbolAddress((void**)&q,    g_q);
    cudaGetSymbolAddress((void**)&k,    g_k);
    cudaGetSymbolAddress((void**)&v,    g_v);
    cudaGetSymbolAddress((void**)&attn, g_attn);

    cudaFuncSetAttribute(flash_fwd, cudaFuncAttributeMaxDynamicSharedMemorySize,
                         FLASH_SMEM_BYTES);

    rope_cache_kernel<<<(SEQ * 64 + 255) / 256, 256>>>();

    dim3 gQKV(DMODEL / 128, MROWS / 128, 3);
    tf32_gemm<<<gQKV, 256>>>(hidden, Wq, Wk, Wv, q, k, v, 1);

    rope_apply_kernel<<<(BH * SEQ * 64 + 255) / 256, 256>>>();

    flash_fwd<<<dim3(SEQ / 64, BH), 128, FLASH_SMEM_BYTES>>>(q, k, v, attn);

    dim3 gO(DMODEL / 128, MROWS / 128, 1);
    tf32_gemm<<<gO, 256>>>(attn, Wo, Wo, Wo, out, out, out, 0);
}